// round 16
// baseline (speedup 1.0000x reference)
#include <cuda_runtime.h>
#include <cuda_bf16.h>
#include <math.h>
#include <stdint.h>

#define BB 32
#define HH 512
#define G4 2048   // 4*HH
#define TT 64
#define VV 32000
#define NBLK 128  // persistent grid for LSTM

// ------------------------- device scratch (no allocs allowed) ----------------
__device__ float g_X1[TT * BB * G4];
__device__ float g_H1[(TT + 1) * BB * HH];
__device__ float g_H2[(TT + 1) * BB * HH];
__device__ int   g_tok[TT * BB];
__device__ unsigned g_bar[2];
__device__ float g_rowsum[TT * BB];               // softmax denominators
__device__ __nv_bfloat16 g_Wb[(size_t)VV * HH];   // bf16 W_out
__device__ __nv_bfloat16 g_Hb[TT * BB * HH];      // bf16 h2 sequence (written by lstm)
__device__ __nv_bfloat16 g_Eb[TT * BB * HH];      // bf16 gathered embeddings
__device__ __nv_bfloat16 g_Wi1b[G4 * HH];         // bf16 W_ih1
__device__ float g_bc1[G4];                       // b_ih1 + b_hh1
__device__ float g_bc2[G4];                       // b_ih2 + b_hh2

// ------------------------- init ---------------------------------------------
__global__ void init_kernel(const int* __restrict__ inputs,
                            const int* __restrict__ targets,
                            const float* __restrict__ hiddens) {
    int i = blockIdx.x * blockDim.x + threadIdx.x;
    if (i == 0) { g_bar[0] = 0u; g_bar[1] = 0u; }
    if (i < TT * BB) g_rowsum[i] = 0.f;
    if (i < BB * HH) {
        g_H2[i] = 0.f;
        g_H1[i] = hiddens[i];
    }
    if (i < TT * BB) {
        int t = i / BB, b = i % BB;
        g_tok[i] = (t == 0) ? inputs[b] : targets[b * TT + (t - 1)];
    }
}

// ------------------------- small converters ----------------------------------
__global__ void cvt_bf16_kernel(const float* __restrict__ src,
                                __nv_bfloat16* __restrict__ dst, int n2) {
    int i = blockIdx.x * blockDim.x + threadIdx.x;
    if (i < n2) {
        float2 v = ((const float2*)src)[i];
        ((__nv_bfloat162*)dst)[i] = __float22bfloat162_rn(v);
    }
}

__global__ void gather_emb_bf16(const float* __restrict__ emb,
                                const int* __restrict__ tok,
                                __nv_bfloat16* __restrict__ dst) {
    int i = blockIdx.x * blockDim.x + threadIdx.x;
    if (i < TT * BB * (HH / 2)) {
        int row = i / (HH / 2);
        int k2 = i % (HH / 2);
        int t = tok[row];
        float2 v = ((const float2*)(emb + (size_t)t * HH))[k2];
        ((__nv_bfloat162*)dst)[i] = __float22bfloat162_rn(v);
    }
}

__global__ void bias_comb_kernel(const float* __restrict__ a,
                                 const float* __restrict__ b,
                                 float* __restrict__ o) {
    int i = blockIdx.x * blockDim.x + threadIdx.x;
    if (i < G4) o[i] = a[i] + b[i];
}

// ------------------------- f32x2 packed FMA helpers --------------------------
#define FFMA2(d, a, b) \
    asm("fma.rn.f32x2 %0, %1, %2, %0;" : "+l"(d) : "l"(a), "l"(b))

__device__ __forceinline__ float hsum2(unsigned long long v) {
    float lo, hi;
    asm("mov.b64 {%0, %1}, %2;" : "=f"(lo), "=f"(hi) : "l"(v));
    return lo + hi;
}

// One thread-tile accumulation pass: 2 gate-rows x 4 batches x 32 k4 (=128 k)
#define ACCUM_PART(acc, wtA, wtB, hvp)                                         \
    _Pragma("unroll 8")                                                        \
    for (int it = 0; it < 32; it++) {                                          \
        const int kk = kbase + it;                                             \
        ulonglong2 w0 = (wtA)[kk];                                             \
        ulonglong2 w1 = (wtB)[kk];                                             \
        const int slot = kk ^ bq;                                              \
        ulonglong2 h0 = (hvp)[(b0 + 0) * 128 + slot];                          \
        ulonglong2 h1 = (hvp)[(b0 + 1) * 128 + slot];                          \
        ulonglong2 h2 = (hvp)[(b0 + 2) * 128 + slot];                          \
        ulonglong2 h3 = (hvp)[(b0 + 3) * 128 + slot];                          \
        FFMA2((acc)[0], w0.x, h0.x); FFMA2((acc)[0], w0.y, h0.y);              \
        FFMA2((acc)[1], w0.x, h1.x); FFMA2((acc)[1], w0.y, h1.y);              \
        FFMA2((acc)[2], w0.x, h2.x); FFMA2((acc)[2], w0.y, h2.y);              \
        FFMA2((acc)[3], w0.x, h3.x); FFMA2((acc)[3], w0.y, h3.y);              \
        FFMA2((acc)[4], w1.x, h0.x); FFMA2((acc)[4], w1.y, h0.y);              \
        FFMA2((acc)[5], w1.x, h1.x); FFMA2((acc)[5], w1.y, h1.y);              \
        FFMA2((acc)[6], w1.x, h2.x); FFMA2((acc)[6], w1.y, h2.y);              \
        FFMA2((acc)[7], w1.x, h3.x); FFMA2((acc)[7], w1.y, h3.y);              \
    }

// ------------------------- fused 2-layer persistent LSTM ---------------------
// One launch runs BOTH layers, software-pipelined: iteration i computes
// h1(i) (layer1) and h2(i-1) (layer2, using h1(i-1) + h2(i-2)). Layer-2's
// input GEMM (h1 @ W_ih2) is computed in-kernel in fp32 — no X2 tensor GEMM,
// no bf16 h1. 65 grid barriers total (vs 128 + launch boundaries).
// SMEM: W_hh1 | W_hh2 | W_ih2 tiles (16x516 each) + hs1 + hs2 (32x128 float4).
// The 24KB reduction buffer aliases the front of hs2 (reads done before write).
#define FUSE_SMEM ((3 * 16 * 516 + 2 * 32 * 512) * 4)   // 230,144 B

__global__ __launch_bounds__(256)
void lstm_fused(const float* __restrict__ X1,    // [TT][BB][G4] x@Wih1^T + bias
                const float* __restrict__ Wh1,   // [G4][HH]
                const float* __restrict__ Wh2,   // [G4][HH]
                const float* __restrict__ Wi2,   // [G4][HH]
                const float* __restrict__ bc2,   // [G4] b_ih2 + b_hh2
                float* __restrict__ H1,          // [(TT+1)][BB][HH]
                float* __restrict__ H2,          // [(TT+1)][BB][HH]
                __nv_bfloat16* __restrict__ Hb2, // [TT*BB][HH] bf16 h2 out
                unsigned* __restrict__ bar) {
    extern __shared__ float sm[];
    float*  Wt1  = sm;                       // [16][516]
    float*  Wt2h = sm + 16 * 516;
    float*  Wt2i = sm + 2 * 16 * 516;
    float4* hs1  = (float4*)(sm + 3 * 16 * 516);   // [32][128] swizzled
    float4* hs2  = hs1 + 32 * 128;
    float*  red  = (float*)hs2;              // alias: 3 x [4][16][32] = 24KB
    float*  redL1  = red;
    float*  redL2h = red + 2048;
    float*  redL2i = red + 4096;

    const int tid = threadIdx.x;
    const int j0 = blockIdx.x * 4;

    // cache the three W tiles once (row r = gate*4 + jj)
    for (int idx = tid; idx < 16 * 512; idx += 256) {
        int r = idx >> 9, k = idx & 511;
        size_t src = (size_t)((r >> 2) * HH + j0 + (r & 3)) * HH + k;
        Wt1[r * 516 + k]  = Wh1[src];
        Wt2h[r * 516 + k] = Wh2[src];
        Wt2i[r * 516 + k] = Wi2[src];
    }

    const int kq = tid >> 6;          // 0..3
    const int rp = (tid >> 3) & 7;    // 0..7
    const int bq = tid & 7;           // 0..7
    const int r0 = rp * 2;
    const int b0 = bq * 4;
    const int kbase = kq * 32;

    const ulonglong2* w1a  = (const ulonglong2*)(Wt1 + r0 * 516);
    const ulonglong2* w1b  = (const ulonglong2*)(Wt1 + (r0 + 1) * 516);
    const ulonglong2* w2ha = (const ulonglong2*)(Wt2h + r0 * 516);
    const ulonglong2* w2hb = (const ulonglong2*)(Wt2h + (r0 + 1) * 516);
    const ulonglong2* w2ia = (const ulonglong2*)(Wt2i + r0 * 516);
    const ulonglong2* w2ib = (const ulonglong2*)(Wt2i + (r0 + 1) * 516);
    const ulonglong2* hv1  = (const ulonglong2*)hs1;
    const ulonglong2* hv2  = (const ulonglong2*)hs2;

    const int fj = (tid >> 5) & 3;
    const int fb = tid & 31;
    float c1 = 0.f, c2 = 0.f;
    float b2i = 0.f, b2f = 0.f, b2g = 0.f, b2o = 0.f;
    if (tid < 128) {
        int j = j0 + fj;
        b2i = bc2[j];
        b2f = bc2[HH + j];
        b2g = bc2[2 * HH + j];
        b2o = bc2[3 * HH + j];
    }

    __syncthreads();

    for (int i = 0; i <= TT; i++) {
        // prefetch X1 gate pre-activations for layer1
        float xi = 0.f, xf = 0.f, xg = 0.f, xo = 0.f;
        if (tid < 128 && i < TT) {
            const float* xp = X1 + ((size_t)i * BB + fb) * G4 + j0 + fj;
            xi = xp[0];
            xf = xp[1 * HH];
            xg = xp[2 * HH];
            xo = xp[3 * HH];
        }

        // load hs1 = h1(i-1) (H1 slot i); hs2 = h2(i-2) (H2 slot i-1)
        const float4* Hp1 = (const float4*)(H1 + (size_t)i * BB * HH);
        const float4* Hp2 = (const float4*)(H2 + (size_t)(i > 0 ? i - 1 : 0) * BB * HH);
#pragma unroll
        for (int l = 0; l < 16; l++) {
            int fid = tid + l * 256;
            int b = fid >> 7, k4 = fid & 127;
            int sl = b * 128 + (k4 ^ (b >> 2));
            hs1[sl] = Hp1[fid];
            hs2[sl] = Hp2[fid];
        }
        __syncthreads();

        unsigned long long aL1[8]  = {0, 0, 0, 0, 0, 0, 0, 0};
        unsigned long long aL2h[8] = {0, 0, 0, 0, 0, 0, 0, 0};
        unsigned long long aL2i[8] = {0, 0, 0, 0, 0, 0, 0, 0};
        if (i > 0) {
            ACCUM_PART(aL2h, w2ha, w2hb, hv2);
            ACCUM_PART(aL2i, w2ia, w2ib, hv1);
        }
        if (i < TT) {
            ACCUM_PART(aL1, w1a, w1b, hv1);
        }
        __syncthreads();   // all hs reads complete -> safe to alias red over hs2

        {
            int base0 = (kq * 16 + r0) * 32 + b0;
            int base1 = (kq * 16 + r0 + 1) * 32 + b0;
            redL1[base0 + 0] = hsum2(aL1[0]); redL1[base0 + 1] = hsum2(aL1[1]);
            redL1[base0 + 2] = hsum2(aL1[2]); redL1[base0 + 3] = hsum2(aL1[3]);
            redL1[base1 + 0] = hsum2(aL1[4]); redL1[base1 + 1] = hsum2(aL1[5]);
            redL1[base1 + 2] = hsum2(aL1[6]); redL1[base1 + 3] = hsum2(aL1[7]);
            redL2h[base0 + 0] = hsum2(aL2h[0]); redL2h[base0 + 1] = hsum2(aL2h[1]);
            redL2h[base0 + 2] = hsum2(aL2h[2]); redL2h[base0 + 3] = hsum2(aL2h[3]);
            redL2h[base1 + 0] = hsum2(aL2h[4]); redL2h[base1 + 1] = hsum2(aL2h[5]);
            redL2h[base1 + 2] = hsum2(aL2h[6]); redL2h[base1 + 3] = hsum2(aL2h[7]);
            redL2i[base0 + 0] = hsum2(aL2i[0]); redL2i[base0 + 1] = hsum2(aL2i[1]);
            redL2i[base0 + 2] = hsum2(aL2i[2]); redL2i[base0 + 3] = hsum2(aL2i[3]);
            redL2i[base1 + 0] = hsum2(aL2i[4]); redL2i[base1 + 1] = hsum2(aL2i[5]);
            redL2i[base1 + 2] = hsum2(aL2i[6]); redL2i[base1 + 3] = hsum2(aL2i[7]);
        }
        __syncthreads();

        if (tid < 128) {
            if (i < TT) {   // layer-1 finalize -> h1(i)
                float gi = xi, gf = xf, gg = xg, go = xo;
#pragma unroll
                for (int q = 0; q < 4; q++) {
                    gi += redL1[(q * 16 + 0  + fj) * 32 + fb];
                    gf += redL1[(q * 16 + 4  + fj) * 32 + fb];
                    gg += redL1[(q * 16 + 8  + fj) * 32 + fb];
                    go += redL1[(q * 16 + 12 + fj) * 32 + fb];
                }
                float iv = 1.f / (1.f + expf(-gi));
                float fv = 1.f / (1.f + expf(-gf));
                float tv = tanhf(gg);
                float ov = 1.f / (1.f + expf(-go));
                c1 = fv * c1 + iv * tv;
                H1[(size_t)(i + 1) * BB * HH + fb * HH + j0 + fj] = ov * tanhf(c1);
            }
            if (i > 0) {    // layer-2 finalize -> h2(i-1)
                float gi = b2i, gf = b2f, gg = b2g, go = b2o;
#pragma unroll
                for (int q = 0; q < 4; q++) {
                    gi += redL2h[(q * 16 + 0  + fj) * 32 + fb] + redL2i[(q * 16 + 0  + fj) * 32 + fb];
                    gf += redL2h[(q * 16 + 4  + fj) * 32 + fb] + redL2i[(q * 16 + 4  + fj) * 32 + fb];
                    gg += redL2h[(q * 16 + 8  + fj) * 32 + fb] + redL2i[(q * 16 + 8  + fj) * 32 + fb];
                    go += redL2h[(q * 16 + 12 + fj) * 32 + fb] + redL2i[(q * 16 + 12 + fj) * 32 + fb];
                }
                float iv = 1.f / (1.f + expf(-gi));
                float fv = 1.f / (1.f + expf(-gf));
                float tv = tanhf(gg);
                float ov = 1.f / (1.f + expf(-go));
                c2 = fv * c2 + iv * tv;
                float hval = ov * tanhf(c2);
                H2[(size_t)i * BB * HH + fb * HH + j0 + fj] = hval;
                Hb2[((size_t)(i - 1) * BB + fb) * HH + j0 + fj] = __float2bfloat16(hval);
            }
        }

        // grid-wide barrier
        __syncthreads();
        if (tid == 0) {
            __threadfence();
            atomicAdd(bar, 1u);
            unsigned target = (unsigned)(i + 1) * (unsigned)gridDim.x;
            while (*(volatile unsigned*)bar < target) { }
            __threadfence();
        }
        __syncthreads();
    }
}

// ------------------------- bf16 mma.sync common ------------------------------
#define LDM_X4(r0, r1, r2, r3, addr)                                           \
    asm volatile("ldmatrix.sync.aligned.m8n8.x4.shared.b16 {%0,%1,%2,%3}, [%4];" \
                 : "=r"(r0), "=r"(r1), "=r"(r2), "=r"(r3) : "r"(addr))

#define MMA_BF16(c, a, b0, b1)                                                 \
    asm volatile(                                                              \
        "mma.sync.aligned.m16n8k16.row.col.f32.bf16.bf16.f32 "                 \
        "{%0,%1,%2,%3}, {%4,%5,%6,%7}, {%8,%9}, {%0,%1,%2,%3};"                \
        : "+f"((c)[0]), "+f"((c)[1]), "+f"((c)[2]), "+f"((c)[3])               \
        : "r"((a)[0]), "r"((a)[1]), "r"((a)[2]), "r"((a)[3]),                  \
          "r"(b0), "r"(b1))

__device__ __forceinline__ uint32_t smem_u32(const void* p) {
    uint32_t a;
    asm("{ .reg .u64 t; cvta.to.shared.u64 t, %1; cvt.u32.u64 %0, t; }"
        : "=r"(a) : "l"(p));
    return a;
}
__device__ __forceinline__ void cp_async16(uint32_t s, const void* g) {
    asm volatile("cp.async.cg.shared.global [%0], [%1], 16;"
                 :: "r"(s), "l"(g) : "memory");
}

#define TROW 80   // padded SMEM row: 40 bf16 = 80 B
#define TBUF (128 * TROW)

// ------------------------- gemm_mma (128x128, X1 path) -----------------------
__global__ __launch_bounds__(256)
void gemm_mma(const __nv_bfloat16* __restrict__ A,
              const __nv_bfloat16* __restrict__ B,
              const float* __restrict__ bias,
              float* __restrict__ C,
              int Kd, int Nd) {
    __shared__ __align__(16) char As[2 * TBUF];
    __shared__ __align__(16) char Bs[2 * TBUF];

    const int tid = threadIdx.x;
    const int lid = tid & 31, wid = tid >> 5;
    const int wm = wid & 3;
    const int wn = wid >> 2;
    const int m0 = blockIdx.y * 128;
    const int n0 = blockIdx.x * 128;

    const uint32_t sA = smem_u32(As);
    const uint32_t sB = smem_u32(Bs);

    const int ldr = tid >> 2;
    const int ldk = (tid & 3) << 3;
    const uint32_t soff = (uint32_t)ldr * TROW + (uint32_t)ldk * 2;

    float acc[2][8][4];
#pragma unroll
    for (int a = 0; a < 2; a++)
#pragma unroll
        for (int b = 0; b < 8; b++)
#pragma unroll
            for (int c = 0; c < 4; c++) acc[a][b][c] = 0.f;

    auto issue = [&](int c, int bf) {
        const int k0 = c * 32 + ldk;
        cp_async16(sA + bf * TBUF + soff,
                   A + (size_t)(m0 + ldr) * Kd + k0);
        cp_async16(sA + bf * TBUF + soff + 64 * TROW,
                   A + (size_t)(m0 + ldr + 64) * Kd + k0);
        cp_async16(sB + bf * TBUF + soff,
                   B + (size_t)(n0 + ldr) * Kd + k0);
        cp_async16(sB + bf * TBUF + soff + 64 * TROW,
                   B + (size_t)(n0 + ldr + 64) * Kd + k0);
        asm volatile("cp.async.commit_group;" ::: "memory");
    };

    issue(0, 0);

    const int a_row = (lid & 15);
    const int a_kh  = (lid >> 4) << 3;
    const int b_j   = lid >> 3;
    const int b_row = ((b_j >> 1) << 3) + (lid & 7);
    const int b_kh  = (b_j & 1) << 3;

    const int nk = Kd >> 5;
    for (int c = 0; c < nk; c++) {
        const int bf = c & 1;
        if (c + 1 < nk) {
            issue(c + 1, bf ^ 1);
            asm volatile("cp.async.wait_group 1;" ::: "memory");
        } else {
            asm volatile("cp.async.wait_group 0;" ::: "memory");
        }
        __syncthreads();

        const uint32_t ab = sA + bf * TBUF;
        const uint32_t bb = sB + bf * TBUF;
#pragma unroll
        for (int ks = 0; ks < 32; ks += 16) {
            uint32_t afr[2][4];
#pragma unroll
            for (int mt = 0; mt < 2; mt++) {
                uint32_t addr = ab + (uint32_t)(wm * 32 + mt * 16 + a_row) * TROW
                              + (uint32_t)(ks + a_kh) * 2;
                LDM_X4(afr[mt][0], afr[mt][1], afr[mt][2], afr[mt][3], addr);
            }
#pragma unroll
            for (int nt16 = 0; nt16 < 4; nt16++) {
                uint32_t b0, b1, b2, b3;
                uint32_t addr = bb + (uint32_t)(wn * 64 + nt16 * 16 + b_row) * TROW
                              + (uint32_t)(ks + b_kh) * 2;
                LDM_X4(b0, b1, b2, b3, addr);
#pragma unroll
                for (int mt = 0; mt < 2; mt++) {
                    MMA_BF16(acc[mt][nt16 * 2 + 0], afr[mt], b0, b1);
                    MMA_BF16(acc[mt][nt16 * 2 + 1], afr[mt], b2, b3);
                }
            }
        }
        __syncthreads();
    }

    const int erow = lid >> 2;
    const int ecol = (lid & 3) << 1;
#pragma unroll
    for (int mt = 0; mt < 2; mt++) {
        const int row = m0 + wm * 32 + mt * 16 + erow;
#pragma unroll
        for (int nt = 0; nt < 8; nt++) {
            const int col = n0 + wn * 64 + nt * 8 + ecol;
            const float bv0 = bias[col], bv1 = bias[col + 1];
            float2 v0 = { acc[mt][nt][0] + bv0, acc[mt][nt][1] + bv1 };
            float2 v1 = { acc[mt][nt][2] + bv0, acc[mt][nt][3] + bv1 };
            *(float2*)&C[(size_t)row * Nd + col] = v0;
            *(float2*)&C[(size_t)(row + 8) * Nd + col] = v1;
        }
    }
}

// ------------------------- gemm_mma_big + fused exp/rowsum (logits path) -----
#define BIG_STAGE ((128 + 256) * TROW)      // 30720 B per stage
#define BIG_SMEM  (2 * BIG_STAGE)           // 61440 B

__global__ __launch_bounds__(256)
void gemm_mma_big(const __nv_bfloat16* __restrict__ A,
                  const __nv_bfloat16* __restrict__ B,
                  const float* __restrict__ bias,
                  float* __restrict__ OUT,
                  float* __restrict__ rowsum,
                  int Kd, int Nd) {
    extern __shared__ __align__(16) char smem_big[];

    const int tid = threadIdx.x;
    const int lid = tid & 31, wid = tid >> 5;
    const int wm = wid & 1;
    const int wn = wid >> 1;
    const int m0 = blockIdx.y * 128;
    const int n0 = blockIdx.x * 256;

    const uint32_t sbase = smem_u32(smem_big);

    float acc[4][8][4];
#pragma unroll
    for (int a = 0; a < 4; a++)
#pragma unroll
        for (int b = 0; b < 8; b++)
#pragma unroll
            for (int c = 0; c < 4; c++) acc[a][b][c] = 0.f;

    auto issue = [&](int c, int bf) {
        const uint32_t st = sbase + bf * BIG_STAGE;
#pragma unroll
        for (int j = 0; j < 6; j++) {
            int cid = tid + j * 256;
            int row = cid >> 2;
            int ck  = cid & 3;
            uint32_t so = (uint32_t)row * TROW + (uint32_t)ck * 16;
            int k0 = c * 32 + ck * 8;
            const __nv_bfloat16* gp;
            if (row < 128) gp = A + (size_t)(m0 + row) * Kd + k0;
            else           gp = B + (size_t)(n0 + row - 128) * Kd + k0;
            cp_async16(st + so, gp);
        }
        asm volatile("cp.async.commit_group;" ::: "memory");
    };

    issue(0, 0);

    const int a_row = (lid & 15);
    const int a_kh  = (lid >> 4) << 3;
    const int b_j   = lid >> 3;
    const int b_row = ((b_j >> 1) << 3) + (lid & 7);
    const int b_kh  = (b_j & 1) << 3;

    const int nk = Kd >> 5;
    for (int c = 0; c < nk; c++) {
        const int bf = c & 1;
        if (c + 1 < nk) {
            issue(c + 1, bf ^ 1);
            asm volatile("cp.async.wait_group 1;" ::: "memory");
        } else {
            asm volatile("cp.async.wait_group 0;" ::: "memory");
        }
        __syncthreads();

        const uint32_t ab = sbase + bf * BIG_STAGE;
        const uint32_t bb = sbase + bf * BIG_STAGE + 128 * TROW;
#pragma unroll
        for (int ks = 0; ks < 32; ks += 16) {
            uint32_t afr[4][4];
#pragma unroll
            for (int mt = 0; mt < 4; mt++) {
                uint32_t addr = ab + (uint32_t)(wm * 64 + mt * 16 + a_row) * TROW
                              + (uint32_t)(ks + a_kh) * 2;
                LDM_X4(afr[mt][0], afr[mt][1], afr[mt][2], afr[mt][3], addr);
            }
#pragma unroll
            for (int nt16 = 0; nt16 < 4; nt16++) {
                uint32_t b0, b1, b2, b3;
                uint32_t addr = bb + (uint32_t)(wn * 64 + nt16 * 16 + b_row) * TROW
                              + (uint32_t)(ks + b_kh) * 2;
                LDM_X4(b0, b1, b2, b3, addr);
#pragma unroll
                for (int mt = 0; mt < 4; mt++) {
                    MMA_BF16(acc[mt][nt16 * 2 + 0], afr[mt], b0, b1);
                    MMA_BF16(acc[mt][nt16 * 2 + 1], afr[mt], b2, b3);
                }
            }
        }
        __syncthreads();
    }

    // fused epilogue: exp + store + per-row partial sums
    const int erow = lid >> 2;
    const int ecol = (lid & 3) << 1;
#pragma unroll
    for (int mt = 0; mt < 4; mt++) {
        const int row = m0 + wm * 64 + mt * 16 + erow;
        float s0 = 0.f, s1 = 0.f;
#pragma unroll
        for (int nt = 0; nt < 8; nt++) {
            const int col = n0 + wn * 64 + nt * 8 + ecol;
            const float bv0 = bias[col], bv1 = bias[col + 1];
            float e00 = __expf(acc[mt][nt][0] + bv0);
            float e01 = __expf(acc[mt][nt][1] + bv1);
            float e10 = __expf(acc[mt][nt][2] + bv0);
            float e11 = __expf(acc[mt][nt][3] + bv1);
            float2 v0 = { e00, e01 };
            float2 v1 = { e10, e11 };
            *(float2*)&OUT[(size_t)row * Nd + col] = v0;
            *(float2*)&OUT[(size_t)(row + 8) * Nd + col] = v1;
            s0 += e00 + e01;
            s1 += e10 + e11;
        }
        s0 += __shfl_xor_sync(0xffffffffu, s0, 1);
        s0 += __shfl_xor_sync(0xffffffffu, s0, 2);
        s1 += __shfl_xor_sync(0xffffffffu, s1, 1);
        s1 += __shfl_xor_sync(0xffffffffu, s1, 2);
        if ((lid & 3) == 0) {
            atomicAdd(&rowsum[row], s0);
            atomicAdd(&rowsum[row + 8], s1);
        }
    }
}

// ------------------------- row scale (softmax pass 2) ------------------------
__global__ __launch_bounds__(256)
void scale_kernel(float* __restrict__ out, const float* __restrict__ rowsum) {
    int r = blockIdx.x;
    float inv = 1.f / rowsum[r];
    float4* p = (float4*)(out + (size_t)r * VV);
    for (int i = threadIdx.x; i < VV / 4; i += 256) {
        float4 v = p[i];
        v.x *= inv; v.y *= inv; v.z *= inv; v.w *= inv;
        p[i] = v;
    }
}

__global__ void copy_h1_kernel(const float* __restrict__ src, float* __restrict__ dst) {
    int i = blockIdx.x * blockDim.x + threadIdx.x;
    if (i < BB * HH) dst[i] = src[i];
}

// ------------------------- host launcher -------------------------------------
static float* sym_f(const void* sym) {
    void* p = nullptr; cudaGetSymbolAddress(&p, sym); return (float*)p;
}
static int* sym_i(const void* sym) {
    void* p = nullptr; cudaGetSymbolAddress(&p, sym); return (int*)p;
}
static unsigned* sym_u(const void* sym) {
    void* p = nullptr; cudaGetSymbolAddress(&p, sym); return (unsigned*)p;
}
static __nv_bfloat16* sym_b(const void* sym) {
    void* p = nullptr; cudaGetSymbolAddress(&p, sym); return (__nv_bfloat16*)p;
}

extern "C" void kernel_launch(void* const* d_in, const int* in_sizes, int n_in,
                              void* d_out, int out_size) {
    const int*   inputs  = (const int*)d_in[0];
    const float* hiddens = (const float*)d_in[1];
    const int*   targets = (const int*)d_in[2];
    const float* emb   = (const float*)d_in[4];
    const float* W_ih1 = (const float*)d_in[5];
    const float* W_hh1 = (const float*)d_in[6];
    const float* b_ih1 = (const float*)d_in[7];
    const float* b_hh1 = (const float*)d_in[8];
    const float* W_ih2 = (const float*)d_in[9];
    const float* W_hh2 = (const float*)d_in[10];
    const float* b_ih2 = (const float*)d_in[11];
    const float* b_hh2 = (const float*)d_in[12];
    const float* W_out = (const float*)d_in[13];
    const float* b_out = (const float*)d_in[14];
    float* out = (float*)d_out;

    float* X1 = sym_f(g_X1);
    float* H1 = sym_f(g_H1);
    float* H2 = sym_f(g_H2);
    float* RS = sym_f(g_rowsum);
    int*   TK = sym_i(g_tok);
    unsigned* BAR = sym_u(g_bar);
    __nv_bfloat16* Wb   = sym_b(g_Wb);
    __nv_bfloat16* Hb   = sym_b(g_Hb);
    __nv_bfloat16* Eb   = sym_b(g_Eb);
    __nv_bfloat16* Wi1b = sym_b(g_Wi1b);
    float* BC1 = sym_f(g_bc1);
    float* BC2 = sym_f(g_bc2);

    cudaFuncSetAttribute(lstm_fused,
                         cudaFuncAttributeMaxDynamicSharedMemorySize, FUSE_SMEM);
    cudaFuncSetAttribute(gemm_mma_big,
                         cudaFuncAttributeMaxDynamicSharedMemorySize, BIG_SMEM);

    // 1) init (token table, states, barrier + rowsum reset)
    init_kernel<<<(BB * HH + 255) / 256, 256>>>(inputs, targets, hiddens);

    // 2) conversions / preps
    cvt_bf16_kernel<<<(VV * HH / 2 + 255) / 256, 256>>>(W_out, Wb, VV * HH / 2);
    cvt_bf16_kernel<<<(G4 * HH / 2 + 255) / 256, 256>>>(W_ih1, Wi1b, G4 * HH / 2);
    bias_comb_kernel<<<(G4 + 255) / 256, 256>>>(b_ih1, b_hh1, BC1);
    bias_comb_kernel<<<(G4 + 255) / 256, 256>>>(b_ih2, b_hh2, BC2);
    gather_emb_bf16<<<(TT * BB * HH / 2 + 255) / 256, 256>>>(emb, TK, Eb);

    // 3) X1 = Eb @ W_ih1^T + (b_ih1 + b_hh1)
    gemm_mma<<<dim3(G4 / 128, (TT * BB) / 128), 256>>>(Eb, Wi1b, BC1, X1, HH, G4);

    // 4) fused 2-layer recurrence (pipelined; writes H1, H2, Hb bf16)
    lstm_fused<<<NBLK, 256, FUSE_SMEM>>>(X1, W_hh1, W_hh2, W_ih2, BC2,
                                         H1, H2, Hb, BAR);

    // 5) probs-unnormalized = exp(h2 @ W_out^T + b_out) -> d_out, rowsums fused
    gemm_mma_big<<<dim3(VV / 256, (TT * BB) / 128), 256, BIG_SMEM>>>(
        Hb, Wb, b_out, out, RS, HH, VV);

    // 6) normalize rows in place
    scale_kernel<<<TT * BB, 256>>>(out, RS);

    // 7) final h1
    long long tbv = (long long)TT * BB * VV;
    if ((long long)out_size >= tbv + (long long)BB * HH) {
        copy_h1_kernel<<<(BB * HH + 255) / 256, 256>>>(H1 + (size_t)TT * BB * HH,
                                                       out + tbv);
    }
}

// round 17
// speedup vs baseline: 1.0197x; 1.0197x over previous
#include <cuda_runtime.h>
#include <cuda_bf16.h>
#include <math.h>
#include <stdint.h>

#define BB 32
#define HH 512
#define G4 2048   // 4*HH
#define TT 64
#define VV 32000
#define NBLK 128  // persistent grid for LSTM

// ------------------------- device scratch (no allocs allowed) ----------------
__device__ float g_X1[TT * BB * G4];
__device__ float g_H1[(TT + 1) * BB * HH];            // fp32 h1 (final h1 output)
__device__ __nv_bfloat16 g_H1b[(TT + 1) * BB * HH];   // bf16 h1 exchange
__device__ __nv_bfloat16 g_H2b[(TT + 1) * BB * HH];   // bf16 h2 exchange + GEMM input
__device__ int   g_tok[TT * BB];
__device__ unsigned g_bar[2];
__device__ float g_rowsum[TT * BB];                   // softmax denominators
__device__ __nv_bfloat16 g_Wb[(size_t)VV * HH];       // bf16 W_out
__device__ __nv_bfloat16 g_Eb[TT * BB * HH];          // bf16 gathered embeddings
__device__ __nv_bfloat16 g_Wi1b[G4 * HH];             // bf16 W_ih1
__device__ float g_bc1[G4];                           // b_ih1 + b_hh1
__device__ float g_bc2[G4];                           // b_ih2 + b_hh2

// ------------------------- init (also folds bias combine) --------------------
__global__ void init_kernel(const int* __restrict__ inputs,
                            const int* __restrict__ targets,
                            const float* __restrict__ hiddens,
                            const float* __restrict__ b_ih1,
                            const float* __restrict__ b_hh1,
                            const float* __restrict__ b_ih2,
                            const float* __restrict__ b_hh2) {
    int i = blockIdx.x * blockDim.x + threadIdx.x;
    if (i == 0) { g_bar[0] = 0u; g_bar[1] = 0u; }
    if (i < TT * BB) g_rowsum[i] = 0.f;
    if (i < G4) {
        g_bc1[i] = b_ih1[i] + b_hh1[i];
        g_bc2[i] = b_ih2[i] + b_hh2[i];
    }
    if (i < BB * HH) {
        float hv = hiddens[i];
        g_H1[i]  = hv;
        g_H1b[i] = __float2bfloat16(hv);
        g_H2b[i] = __float2bfloat16(0.f);
    }
    if (i < TT * BB) {
        int t = i / BB, b = i % BB;
        g_tok[i] = (t == 0) ? inputs[b] : targets[b * TT + (t - 1)];
    }
}

// ------------------------- small converters ----------------------------------
__global__ void cvt_bf16_kernel(const float* __restrict__ src,
                                __nv_bfloat16* __restrict__ dst, int n2) {
    int i = blockIdx.x * blockDim.x + threadIdx.x;
    if (i < n2) {
        float2 v = ((const float2*)src)[i];
        ((__nv_bfloat162*)dst)[i] = __float22bfloat162_rn(v);
    }
}

__global__ void gather_emb_bf16(const float* __restrict__ emb,
                                const int* __restrict__ tok,
                                __nv_bfloat16* __restrict__ dst) {
    int i = blockIdx.x * blockDim.x + threadIdx.x;
    if (i < TT * BB * (HH / 2)) {
        int row = i / (HH / 2);
        int k2 = i % (HH / 2);
        int t = tok[row];
        float2 v = ((const float2*)(emb + (size_t)t * HH))[k2];
        ((__nv_bfloat162*)dst)[i] = __float22bfloat162_rn(v);
    }
}

// ------------------------- f32x2 packed FMA helpers --------------------------
#define FFMA2(d, a, b) \
    asm("fma.rn.f32x2 %0, %1, %2, %0;" : "+l"(d) : "l"(a), "l"(b))

__device__ __forceinline__ float hsum2(unsigned long long v) {
    float lo, hi;
    asm("mov.b64 {%0, %1}, %2;" : "=f"(lo), "=f"(hi) : "l"(v));
    return lo + hi;
}

// One thread-tile accumulation pass: 2 gate-rows x 4 batches x 32 k4 (=128 k)
#define ACCUM_PART(acc, wtA, wtB, hvp)                                         \
    _Pragma("unroll 8")                                                        \
    for (int it = 0; it < 32; it++) {                                          \
        const int kk = kbase + it;                                             \
        ulonglong2 w0 = (wtA)[kk];                                             \
        ulonglong2 w1 = (wtB)[kk];                                             \
        const int slot = kk ^ bq;                                              \
        ulonglong2 h0 = (hvp)[(b0 + 0) * 128 + slot];                          \
        ulonglong2 h1 = (hvp)[(b0 + 1) * 128 + slot];                          \
        ulonglong2 h2 = (hvp)[(b0 + 2) * 128 + slot];                          \
        ulonglong2 h3 = (hvp)[(b0 + 3) * 128 + slot];                          \
        FFMA2((acc)[0], w0.x, h0.x); FFMA2((acc)[0], w0.y, h0.y);              \
        FFMA2((acc)[1], w0.x, h1.x); FFMA2((acc)[1], w0.y, h1.y);              \
        FFMA2((acc)[2], w0.x, h2.x); FFMA2((acc)[2], w0.y, h2.y);              \
        FFMA2((acc)[3], w0.x, h3.x); FFMA2((acc)[3], w0.y, h3.y);              \
        FFMA2((acc)[4], w1.x, h0.x); FFMA2((acc)[4], w1.y, h0.y);              \
        FFMA2((acc)[5], w1.x, h1.x); FFMA2((acc)[5], w1.y, h1.y);              \
        FFMA2((acc)[6], w1.x, h2.x); FFMA2((acc)[6], w1.y, h2.y);              \
        FFMA2((acc)[7], w1.x, h3.x); FFMA2((acc)[7], w1.y, h3.y);              \
    }

// unpack a uint4 of 8 bf16 into two float4 (exact: bf16 = top bits of f32)
#define UNPACK8(v, f0, f1)                                                     \
    do {                                                                       \
        (f0).x = __uint_as_float((v).x << 16);                                 \
        (f0).y = __uint_as_float((v).x & 0xffff0000u);                         \
        (f0).z = __uint_as_float((v).y << 16);                                 \
        (f0).w = __uint_as_float((v).y & 0xffff0000u);                         \
        (f1).x = __uint_as_float((v).z << 16);                                 \
        (f1).y = __uint_as_float((v).z & 0xffff0000u);                         \
        (f1).z = __uint_as_float((v).w << 16);                                 \
        (f1).w = __uint_as_float((v).w & 0xffff0000u);                         \
    } while (0)

// ------------------------- fused 2-layer persistent LSTM ---------------------
// Iteration i computes h1(i) (layer1) and h2(i-1) (layer2). h circulates in
// bf16 (halves the per-step 16MB L2 broadcast). Layer-2 ih GEMM in-kernel.
#define FUSE_SMEM ((3 * 16 * 516 + 2 * 32 * 512) * 4)   // 230,144 B

__global__ __launch_bounds__(256)
void lstm_fused(const float* __restrict__ X1,    // [TT][BB][G4] x@Wih1^T + bias
                const float* __restrict__ Wh1,   // [G4][HH]
                const float* __restrict__ Wh2,   // [G4][HH]
                const float* __restrict__ Wi2,   // [G4][HH]
                const float* __restrict__ bc2,   // [G4]
                float* __restrict__ H1,          // [(TT+1)][BB][HH] fp32
                __nv_bfloat16* __restrict__ H1b, // [(TT+1)][BB][HH]
                __nv_bfloat16* __restrict__ H2b, // [(TT+1)][BB][HH]
                unsigned* __restrict__ bar) {
    extern __shared__ float sm[];
    float*  Wt1  = sm;                       // [16][516]
    float*  Wt2h = sm + 16 * 516;
    float*  Wt2i = sm + 2 * 16 * 516;
    float4* hs1  = (float4*)(sm + 3 * 16 * 516);   // [32][128] swizzled
    float4* hs2  = hs1 + 32 * 128;
    float*  red  = (float*)hs2;              // alias: 3 x [4][16][32] = 24KB
    float*  redL1  = red;
    float*  redL2h = red + 2048;
    float*  redL2i = red + 4096;

    const int tid = threadIdx.x;
    const int j0 = blockIdx.x * 4;

    for (int idx = tid; idx < 16 * 512; idx += 256) {
        int r = idx >> 9, k = idx & 511;
        size_t src = (size_t)((r >> 2) * HH + j0 + (r & 3)) * HH + k;
        Wt1[r * 516 + k]  = Wh1[src];
        Wt2h[r * 516 + k] = Wh2[src];
        Wt2i[r * 516 + k] = Wi2[src];
    }

    const int kq = tid >> 6;
    const int rp = (tid >> 3) & 7;
    const int bq = tid & 7;
    const int r0 = rp * 2;
    const int b0 = bq * 4;
    const int kbase = kq * 32;

    const ulonglong2* w1a  = (const ulonglong2*)(Wt1 + r0 * 516);
    const ulonglong2* w1b  = (const ulonglong2*)(Wt1 + (r0 + 1) * 516);
    const ulonglong2* w2ha = (const ulonglong2*)(Wt2h + r0 * 516);
    const ulonglong2* w2hb = (const ulonglong2*)(Wt2h + (r0 + 1) * 516);
    const ulonglong2* w2ia = (const ulonglong2*)(Wt2i + r0 * 516);
    const ulonglong2* w2ib = (const ulonglong2*)(Wt2i + (r0 + 1) * 516);
    const ulonglong2* hv1  = (const ulonglong2*)hs1;
    const ulonglong2* hv2  = (const ulonglong2*)hs2;

    const int fj = (tid >> 5) & 3;
    const int fb = tid & 31;
    float c1 = 0.f, c2 = 0.f;
    float b2i = 0.f, b2f = 0.f, b2g = 0.f, b2o = 0.f;
    if (tid < 128) {
        int j = j0 + fj;
        b2i = bc2[j];
        b2f = bc2[HH + j];
        b2g = bc2[2 * HH + j];
        b2o = bc2[3 * HH + j];
    }

    __syncthreads();

    for (int i = 0; i <= TT; i++) {
        float xi = 0.f, xf = 0.f, xg = 0.f, xo = 0.f;
        if (tid < 128 && i < TT) {
            const float* xp = X1 + ((size_t)i * BB + fb) * G4 + j0 + fj;
            xi = xp[0];
            xf = xp[1 * HH];
            xg = xp[2 * HH];
            xo = xp[3 * HH];
        }

        // load hs1 = h1(i-1) (slot i); hs2 = h2(i-2) (slot i-1), bf16 -> fp32
        const uint4* Hp1 = (const uint4*)(H1b + (size_t)i * BB * HH);
        const uint4* Hp2 = (const uint4*)(H2b + (size_t)(i > 0 ? i - 1 : 0) * BB * HH);
#pragma unroll
        for (int l = 0; l < 8; l++) {
            int fid = tid + l * 256;          // 2048 chunks of 8 bf16
            int b = fid >> 6;
            int k8 = fid & 63;
            int k4 = k8 * 2;
            int sw = b >> 2;
            int s0 = b * 128 + (k4 ^ sw);
            int s1 = b * 128 + ((k4 + 1) ^ sw);
            uint4 v1 = Hp1[fid];
            float4 f0, f1;
            UNPACK8(v1, f0, f1);
            hs1[s0] = f0; hs1[s1] = f1;
            uint4 v2 = Hp2[fid];
            UNPACK8(v2, f0, f1);
            hs2[s0] = f0; hs2[s1] = f1;
        }
        __syncthreads();

        unsigned long long aL1[8]  = {0, 0, 0, 0, 0, 0, 0, 0};
        unsigned long long aL2h[8] = {0, 0, 0, 0, 0, 0, 0, 0};
        unsigned long long aL2i[8] = {0, 0, 0, 0, 0, 0, 0, 0};
        if (i > 0) {
            ACCUM_PART(aL2h, w2ha, w2hb, hv2);
            ACCUM_PART(aL2i, w2ia, w2ib, hv1);
        }
        if (i < TT) {
            ACCUM_PART(aL1, w1a, w1b, hv1);
        }
        __syncthreads();   // hs reads done -> safe to alias red over hs2

        {
            int base0 = (kq * 16 + r0) * 32 + b0;
            int base1 = (kq * 16 + r0 + 1) * 32 + b0;
            redL1[base0 + 0] = hsum2(aL1[0]); redL1[base0 + 1] = hsum2(aL1[1]);
            redL1[base0 + 2] = hsum2(aL1[2]); redL1[base0 + 3] = hsum2(aL1[3]);
            redL1[base1 + 0] = hsum2(aL1[4]); redL1[base1 + 1] = hsum2(aL1[5]);
            redL1[base1 + 2] = hsum2(aL1[6]); redL1[base1 + 3] = hsum2(aL1[7]);
            redL2h[base0 + 0] = hsum2(aL2h[0]); redL2h[base0 + 1] = hsum2(aL2h[1]);
            redL2h[base0 + 2] = hsum2(aL2h[2]); redL2h[base0 + 3] = hsum2(aL2h[3]);
            redL2h[base1 + 0] = hsum2(aL2h[4]); redL2h[base1 + 1] = hsum2(aL2h[5]);
            redL2h[base1 + 2] = hsum2(aL2h[6]); redL2h[base1 + 3] = hsum2(aL2h[7]);
            redL2i[base0 + 0] = hsum2(aL2i[0]); redL2i[base0 + 1] = hsum2(aL2i[1]);
            redL2i[base0 + 2] = hsum2(aL2i[2]); redL2i[base0 + 3] = hsum2(aL2i[3]);
            redL2i[base1 + 0] = hsum2(aL2i[4]); redL2i[base1 + 1] = hsum2(aL2i[5]);
            redL2i[base1 + 2] = hsum2(aL2i[6]); redL2i[base1 + 3] = hsum2(aL2i[7]);
        }
        __syncthreads();

        if (tid < 128) {
            if (i < TT) {   // layer-1 finalize -> h1(i)
                float gi = xi, gf = xf, gg = xg, go = xo;
#pragma unroll
                for (int q = 0; q < 4; q++) {
                    gi += redL1[(q * 16 + 0  + fj) * 32 + fb];
                    gf += redL1[(q * 16 + 4  + fj) * 32 + fb];
                    gg += redL1[(q * 16 + 8  + fj) * 32 + fb];
                    go += redL1[(q * 16 + 12 + fj) * 32 + fb];
                }
                float iv = 1.f / (1.f + expf(-gi));
                float fv = 1.f / (1.f + expf(-gf));
                float tv = tanhf(gg);
                float ov = 1.f / (1.f + expf(-go));
                c1 = fv * c1 + iv * tv;
                float hval = ov * tanhf(c1);
                size_t off = (size_t)(i + 1) * BB * HH + fb * HH + j0 + fj;
                H1[off] = hval;
                H1b[off] = __float2bfloat16(hval);
            }
            if (i > 0) {    // layer-2 finalize -> h2(i-1)
                float gi = b2i, gf = b2f, gg = b2g, go = b2o;
#pragma unroll
                for (int q = 0; q < 4; q++) {
                    gi += redL2h[(q * 16 + 0  + fj) * 32 + fb] + redL2i[(q * 16 + 0  + fj) * 32 + fb];
                    gf += redL2h[(q * 16 + 4  + fj) * 32 + fb] + redL2i[(q * 16 + 4  + fj) * 32 + fb];
                    gg += redL2h[(q * 16 + 8  + fj) * 32 + fb] + redL2i[(q * 16 + 8  + fj) * 32 + fb];
                    go += redL2h[(q * 16 + 12 + fj) * 32 + fb] + redL2i[(q * 16 + 12 + fj) * 32 + fb];
                }
                float iv = 1.f / (1.f + expf(-gi));
                float fv = 1.f / (1.f + expf(-gf));
                float tv = tanhf(gg);
                float ov = 1.f / (1.f + expf(-go));
                c2 = fv * c2 + iv * tv;
                float hval = ov * tanhf(c2);
                H2b[(size_t)i * BB * HH + fb * HH + j0 + fj] = __float2bfloat16(hval);
            }
        }

        __syncthreads();
        if (tid == 0) {
            __threadfence();
            atomicAdd(bar, 1u);
            unsigned target = (unsigned)(i + 1) * (unsigned)gridDim.x;
            while (*(volatile unsigned*)bar < target) { }
            __threadfence();
        }
        __syncthreads();
    }
}

// ------------------------- bf16 mma.sync common ------------------------------
#define LDM_X4(r0, r1, r2, r3, addr)                                           \
    asm volatile("ldmatrix.sync.aligned.m8n8.x4.shared.b16 {%0,%1,%2,%3}, [%4];" \
                 : "=r"(r0), "=r"(r1), "=r"(r2), "=r"(r3) : "r"(addr))

#define MMA_BF16(c, a, b0, b1)                                                 \
    asm volatile(                                                              \
        "mma.sync.aligned.m16n8k16.row.col.f32.bf16.bf16.f32 "                 \
        "{%0,%1,%2,%3}, {%4,%5,%6,%7}, {%8,%9}, {%0,%1,%2,%3};"                \
        : "+f"((c)[0]), "+f"((c)[1]), "+f"((c)[2]), "+f"((c)[3])               \
        : "r"((a)[0]), "r"((a)[1]), "r"((a)[2]), "r"((a)[3]),                  \
          "r"(b0), "r"(b1))

__device__ __forceinline__ uint32_t smem_u32(const void* p) {
    uint32_t a;
    asm("{ .reg .u64 t; cvta.to.shared.u64 t, %1; cvt.u32.u64 %0, t; }"
        : "=r"(a) : "l"(p));
    return a;
}
__device__ __forceinline__ void cp_async16(uint32_t s, const void* g) {
    asm volatile("cp.async.cg.shared.global [%0], [%1], 16;"
                 :: "r"(s), "l"(g) : "memory");
}

#define TROW 80   // padded SMEM row: 40 bf16 = 80 B
#define TBUF (128 * TROW)

// ------------------------- gemm_mma (128x128, X1 path) -----------------------
__global__ __launch_bounds__(256)
void gemm_mma(const __nv_bfloat16* __restrict__ A,
              const __nv_bfloat16* __restrict__ B,
              const float* __restrict__ bias,
              float* __restrict__ C,
              int Kd, int Nd) {
    __shared__ __align__(16) char As[2 * TBUF];
    __shared__ __align__(16) char Bs[2 * TBUF];

    const int tid = threadIdx.x;
    const int lid = tid & 31, wid = tid >> 5;
    const int wm = wid & 3;
    const int wn = wid >> 2;
    const int m0 = blockIdx.y * 128;
    const int n0 = blockIdx.x * 128;

    const uint32_t sA = smem_u32(As);
    const uint32_t sB = smem_u32(Bs);

    const int ldr = tid >> 2;
    const int ldk = (tid & 3) << 3;
    const uint32_t soff = (uint32_t)ldr * TROW + (uint32_t)ldk * 2;

    float acc[2][8][4];
#pragma unroll
    for (int a = 0; a < 2; a++)
#pragma unroll
        for (int b = 0; b < 8; b++)
#pragma unroll
            for (int c = 0; c < 4; c++) acc[a][b][c] = 0.f;

    auto issue = [&](int c, int bf) {
        const int k0 = c * 32 + ldk;
        cp_async16(sA + bf * TBUF + soff,
                   A + (size_t)(m0 + ldr) * Kd + k0);
        cp_async16(sA + bf * TBUF + soff + 64 * TROW,
                   A + (size_t)(m0 + ldr + 64) * Kd + k0);
        cp_async16(sB + bf * TBUF + soff,
                   B + (size_t)(n0 + ldr) * Kd + k0);
        cp_async16(sB + bf * TBUF + soff + 64 * TROW,
                   B + (size_t)(n0 + ldr + 64) * Kd + k0);
        asm volatile("cp.async.commit_group;" ::: "memory");
    };

    issue(0, 0);

    const int a_row = (lid & 15);
    const int a_kh  = (lid >> 4) << 3;
    const int b_j   = lid >> 3;
    const int b_row = ((b_j >> 1) << 3) + (lid & 7);
    const int b_kh  = (b_j & 1) << 3;

    const int nk = Kd >> 5;
    for (int c = 0; c < nk; c++) {
        const int bf = c & 1;
        if (c + 1 < nk) {
            issue(c + 1, bf ^ 1);
            asm volatile("cp.async.wait_group 1;" ::: "memory");
        } else {
            asm volatile("cp.async.wait_group 0;" ::: "memory");
        }
        __syncthreads();

        const uint32_t ab = sA + bf * TBUF;
        const uint32_t bb = sB + bf * TBUF;
#pragma unroll
        for (int ks = 0; ks < 32; ks += 16) {
            uint32_t afr[2][4];
#pragma unroll
            for (int mt = 0; mt < 2; mt++) {
                uint32_t addr = ab + (uint32_t)(wm * 32 + mt * 16 + a_row) * TROW
                              + (uint32_t)(ks + a_kh) * 2;
                LDM_X4(afr[mt][0], afr[mt][1], afr[mt][2], afr[mt][3], addr);
            }
#pragma unroll
            for (int nt16 = 0; nt16 < 4; nt16++) {
                uint32_t b0, b1, b2, b3;
                uint32_t addr = bb + (uint32_t)(wn * 64 + nt16 * 16 + b_row) * TROW
                              + (uint32_t)(ks + b_kh) * 2;
                LDM_X4(b0, b1, b2, b3, addr);
#pragma unroll
                for (int mt = 0; mt < 2; mt++) {
                    MMA_BF16(acc[mt][nt16 * 2 + 0], afr[mt], b0, b1);
                    MMA_BF16(acc[mt][nt16 * 2 + 1], afr[mt], b2, b3);
                }
            }
        }
        __syncthreads();
    }

    const int erow = lid >> 2;
    const int ecol = (lid & 3) << 1;
#pragma unroll
    for (int mt = 0; mt < 2; mt++) {
        const int row = m0 + wm * 32 + mt * 16 + erow;
#pragma unroll
        for (int nt = 0; nt < 8; nt++) {
            const int col = n0 + wn * 64 + nt * 8 + ecol;
            const float bv0 = bias[col], bv1 = bias[col + 1];
            float2 v0 = { acc[mt][nt][0] + bv0, acc[mt][nt][1] + bv1 };
            float2 v1 = { acc[mt][nt][2] + bv0, acc[mt][nt][3] + bv1 };
            *(float2*)&C[(size_t)row * Nd + col] = v0;
            *(float2*)&C[(size_t)(row + 8) * Nd + col] = v1;
        }
    }
}

// ------------------------- gemm_mma_big + fused exp/rowsum (logits path) -----
#define BIG_STAGE ((128 + 256) * TROW)      // 30720 B per stage
#define BIG_SMEM  (2 * BIG_STAGE)           // 61440 B

__global__ __launch_bounds__(256)
void gemm_mma_big(const __nv_bfloat16* __restrict__ A,
                  const __nv_bfloat16* __restrict__ B,
                  const float* __restrict__ bias,
                  float* __restrict__ OUT,
                  float* __restrict__ rowsum,
                  int Kd, int Nd) {
    extern __shared__ __align__(16) char smem_big[];

    const int tid = threadIdx.x;
    const int lid = tid & 31, wid = tid >> 5;
    const int wm = wid & 1;
    const int wn = wid >> 1;
    const int m0 = blockIdx.y * 128;
    const int n0 = blockIdx.x * 256;

    const uint32_t sbase = smem_u32(smem_big);

    float acc[4][8][4];
#pragma unroll
    for (int a = 0; a < 4; a++)
#pragma unroll
        for (int b = 0; b < 8; b++)
#pragma unroll
            for (int c = 0; c < 4; c++) acc[a][b][c] = 0.f;

    auto issue = [&](int c, int bf) {
        const uint32_t st = sbase + bf * BIG_STAGE;
#pragma unroll
        for (int j = 0; j < 6; j++) {
            int cid = tid + j * 256;
            int row = cid >> 2;
            int ck  = cid & 3;
            uint32_t so = (uint32_t)row * TROW + (uint32_t)ck * 16;
            int k0 = c * 32 + ck * 8;
            const __nv_bfloat16* gp;
            if (row < 128) gp = A + (size_t)(m0 + row) * Kd + k0;
            else           gp = B + (size_t)(n0 + row - 128) * Kd + k0;
            cp_async16(st + so, gp);
        }
        asm volatile("cp.async.commit_group;" ::: "memory");
    };

    issue(0, 0);

    const int a_row = (lid & 15);
    const int a_kh  = (lid >> 4) << 3;
    const int b_j   = lid >> 3;
    const int b_row = ((b_j >> 1) << 3) + (lid & 7);
    const int b_kh  = (b_j & 1) << 3;

    const int nk = Kd >> 5;
    for (int c = 0; c < nk; c++) {
        const int bf = c & 1;
        if (c + 1 < nk) {
            issue(c + 1, bf ^ 1);
            asm volatile("cp.async.wait_group 1;" ::: "memory");
        } else {
            asm volatile("cp.async.wait_group 0;" ::: "memory");
        }
        __syncthreads();

        const uint32_t ab = sbase + bf * BIG_STAGE;
        const uint32_t bb = sbase + bf * BIG_STAGE + 128 * TROW;
#pragma unroll
        for (int ks = 0; ks < 32; ks += 16) {
            uint32_t afr[4][4];
#pragma unroll
            for (int mt = 0; mt < 4; mt++) {
                uint32_t addr = ab + (uint32_t)(wm * 64 + mt * 16 + a_row) * TROW
                              + (uint32_t)(ks + a_kh) * 2;
                LDM_X4(afr[mt][0], afr[mt][1], afr[mt][2], afr[mt][3], addr);
            }
#pragma unroll
            for (int nt16 = 0; nt16 < 4; nt16++) {
                uint32_t b0, b1, b2, b3;
                uint32_t addr = bb + (uint32_t)(wn * 64 + nt16 * 16 + b_row) * TROW
                              + (uint32_t)(ks + b_kh) * 2;
                LDM_X4(b0, b1, b2, b3, addr);
#pragma unroll
                for (int mt = 0; mt < 4; mt++) {
                    MMA_BF16(acc[mt][nt16 * 2 + 0], afr[mt], b0, b1);
                    MMA_BF16(acc[mt][nt16 * 2 + 1], afr[mt], b2, b3);
                }
            }
        }
        __syncthreads();
    }

    const int erow = lid >> 2;
    const int ecol = (lid & 3) << 1;
#pragma unroll
    for (int mt = 0; mt < 4; mt++) {
        const int row = m0 + wm * 64 + mt * 16 + erow;
        float s0 = 0.f, s1 = 0.f;
#pragma unroll
        for (int nt = 0; nt < 8; nt++) {
            const int col = n0 + wn * 64 + nt * 8 + ecol;
            const float bv0 = bias[col], bv1 = bias[col + 1];
            float e00 = __expf(acc[mt][nt][0] + bv0);
            float e01 = __expf(acc[mt][nt][1] + bv1);
            float e10 = __expf(acc[mt][nt][2] + bv0);
            float e11 = __expf(acc[mt][nt][3] + bv1);
            float2 v0 = { e00, e01 };
            float2 v1 = { e10, e11 };
            *(float2*)&OUT[(size_t)row * Nd + col] = v0;
            *(float2*)&OUT[(size_t)(row + 8) * Nd + col] = v1;
            s0 += e00 + e01;
            s1 += e10 + e11;
        }
        s0 += __shfl_xor_sync(0xffffffffu, s0, 1);
        s0 += __shfl_xor_sync(0xffffffffu, s0, 2);
        s1 += __shfl_xor_sync(0xffffffffu, s1, 1);
        s1 += __shfl_xor_sync(0xffffffffu, s1, 2);
        if ((lid & 3) == 0) {
            atomicAdd(&rowsum[row], s0);
            atomicAdd(&rowsum[row + 8], s1);
        }
    }
}

// ------------------------- row scale (softmax pass 2) ------------------------
__global__ __launch_bounds__(256)
void scale_kernel(float* __restrict__ out, const float* __restrict__ rowsum) {
    int r = blockIdx.x;
    float inv = 1.f / rowsum[r];
    float4* p = (float4*)(out + (size_t)r * VV);
    for (int i = threadIdx.x; i < VV / 4; i += 256) {
        float4 v = p[i];
        v.x *= inv; v.y *= inv; v.z *= inv; v.w *= inv;
        p[i] = v;
    }
}

__global__ void copy_h1_kernel(const float* __restrict__ src, float* __restrict__ dst) {
    int i = blockIdx.x * blockDim.x + threadIdx.x;
    if (i < BB * HH) dst[i] = src[i];
}

// ------------------------- host launcher -------------------------------------
static float* sym_f(const void* sym) {
    void* p = nullptr; cudaGetSymbolAddress(&p, sym); return (float*)p;
}
static int* sym_i(const void* sym) {
    void* p = nullptr; cudaGetSymbolAddress(&p, sym); return (int*)p;
}
static unsigned* sym_u(const void* sym) {
    void* p = nullptr; cudaGetSymbolAddress(&p, sym); return (unsigned*)p;
}
static __nv_bfloat16* sym_b(const void* sym) {
    void* p = nullptr; cudaGetSymbolAddress(&p, sym); return (__nv_bfloat16*)p;
}

extern "C" void kernel_launch(void* const* d_in, const int* in_sizes, int n_in,
                              void* d_out, int out_size) {
    const int*   inputs  = (const int*)d_in[0];
    const float* hiddens = (const float*)d_in[1];
    const int*   targets = (const int*)d_in[2];
    const float* emb   = (const float*)d_in[4];
    const float* W_ih1 = (const float*)d_in[5];
    const float* W_hh1 = (const float*)d_in[6];
    const float* b_ih1 = (const float*)d_in[7];
    const float* b_hh1 = (const float*)d_in[8];
    const float* W_ih2 = (const float*)d_in[9];
    const float* W_hh2 = (const float*)d_in[10];
    const float* b_ih2 = (const float*)d_in[11];
    const float* b_hh2 = (const float*)d_in[12];
    const float* W_out = (const float*)d_in[13];
    const float* b_out = (const float*)d_in[14];
    float* out = (float*)d_out;

    float* X1 = sym_f(g_X1);
    float* H1 = sym_f(g_H1);
    float* RS = sym_f(g_rowsum);
    int*   TK = sym_i(g_tok);
    unsigned* BAR = sym_u(g_bar);
    __nv_bfloat16* H1B  = sym_b(g_H1b);
    __nv_bfloat16* H2B  = sym_b(g_H2b);
    __nv_bfloat16* Wb   = sym_b(g_Wb);
    __nv_bfloat16* Eb   = sym_b(g_Eb);
    __nv_bfloat16* Wi1b = sym_b(g_Wi1b);
    float* BC1 = sym_f(g_bc1);
    float* BC2 = sym_f(g_bc2);

    cudaFuncSetAttribute(lstm_fused,
                         cudaFuncAttributeMaxDynamicSharedMemorySize, FUSE_SMEM);
    cudaFuncSetAttribute(gemm_mma_big,
                         cudaFuncAttributeMaxDynamicSharedMemorySize, BIG_SMEM);

    // Launch order chosen so lstm_fused is the 6th launch (ncu -s 5 -c 1).
    // 1) init: states + tok + combined biases + barrier/rowsum reset
    init_kernel<<<(BB * HH + 255) / 256, 256>>>(inputs, targets, hiddens,
                                                b_ih1, b_hh1, b_ih2, b_hh2);

    // 2-4) conversions / gather
    cvt_bf16_kernel<<<(VV * HH / 2 + 255) / 256, 256>>>(W_out, Wb, VV * HH / 2);
    cvt_bf16_kernel<<<(G4 * HH / 2 + 255) / 256, 256>>>(W_ih1, Wi1b, G4 * HH / 2);
    gather_emb_bf16<<<(TT * BB * HH / 2 + 255) / 256, 256>>>(emb, TK, Eb);

    // 5) X1 = Eb @ W_ih1^T + (b_ih1 + b_hh1)
    gemm_mma<<<dim3(G4 / 128, (TT * BB) / 128), 256>>>(Eb, Wi1b, BC1, X1, HH, G4);

    // 6) fused 2-layer recurrence (bf16 h exchange)
    lstm_fused<<<NBLK, 256, FUSE_SMEM>>>(X1, W_hh1, W_hh2, W_ih2, BC2,
                                         H1, H1B, H2B, BAR);

    // 7) probs-unnormalized = exp(h2 @ W_out^T + b_out) -> d_out, rowsums fused
    gemm_mma_big<<<dim3(VV / 256, (TT * BB) / 128), 256, BIG_SMEM>>>(
        H2B + BB * HH, Wb, b_out, out, RS, HH, VV);

    // 8) normalize rows in place
    scale_kernel<<<TT * BB, 256>>>(out, RS);

    // 9) final h1
    long long tbv = (long long)TT * BB * VV;
    if ((long long)out_size >= tbv + (long long)BB * HH) {
        copy_h1_kernel<<<(BB * HH + 255) / 256, 256>>>(H1 + (size_t)TT * BB * HH,
                                                       out + tbv);
    }
}